// round 5
// baseline (speedup 1.0000x reference)
#include <cuda_runtime.h>
#include <cstdint>

#define NN 40000
#define NE 640000

// ---- device scratch ----
__device__ __align__(128) float g_buf[NN * 64];
__device__ __align__(128) float h_buf[NN * 64];
__device__ __align__(128) float w23_buf[128 * 64];
__device__ __align__(128) float w123_buf[128 * 64];
__device__ int g_rowptr[NN + 1];

typedef unsigned long long u64;

#define FMA_F32X2(d, a, b) \
    asm("fma.rn.f32x2 %0, %1, %2, %0;" : "+l"(d) : "l"(a), "l"(b))
#define DUP_F32X2(d, f) \
    asm("mov.b64 %0, {%1, %1};" : "=l"(d) : "r"(__float_as_uint(f)))

// ---------------------------------------------------------------------------
// CSR row pointers from SORTED dst: row_ptr[n] = lower_bound(dst, n)
// ---------------------------------------------------------------------------
__global__ void build_rowptr(const int* __restrict__ dst) {
    int n = blockIdx.x * blockDim.x + threadIdx.x;
    if (n > NN) return;
    int lo = 0, hi = NE;
    while (lo < hi) {
        int mid = (lo + hi) >> 1;
        if (dst[mid] < n) lo = mid + 1; else hi = mid;
    }
    g_rowptr[n] = lo;
}

// ---------------------------------------------------------------------------
// Small matmul C[128,64] = A[128,128] @ B[128,64], B staged in smem.
// grid=32 x 256 threads, one output element per thread.
// ---------------------------------------------------------------------------
__global__ void __launch_bounds__(256)
mm128x64(const float* __restrict__ A, const float* __restrict__ B,
         float* __restrict__ C) {
    __shared__ float sB[128 * 64];
    int tid = threadIdx.x;
    for (int i = tid * 4; i < 128 * 64; i += 256 * 4)
        *(float4*)&sB[i] = *(const float4*)&B[i];
    __syncthreads();

    int idx = blockIdx.x * 256 + tid;
    int i = idx >> 6, j = idx & 63;
    float acc = 0.f;
    #pragma unroll 8
    for (int k = 0; k < 128; k++)
        acc += __ldg(&A[i * 128 + k]) * sB[k * 64 + j];
    C[idx] = acc;
}

// ---------------------------------------------------------------------------
// GEMM: X[N,64] = F[N,128] @ W[128,64], packed fma.rn.f32x2.
// 512 threads, microtile 2 rows x 8 cols (4 f32x2 pairs), block = 128 rows.
// launch_bounds(512,2) -> <=64 regs -> 32 warps/SM.
// ---------------------------------------------------------------------------
__global__ void __launch_bounds__(512, 2)
gemm64(const float* __restrict__ H, const float* __restrict__ W,
       float* __restrict__ G) {
    __shared__ float sW[128 * 64];

    const int tid = threadIdx.x;
    for (int i = tid * 4; i < 128 * 64; i += 512 * 4)
        *(float4*)&sW[i] = *(const float4*)&W[i];
    __syncthreads();

    const int tx = tid & 7;            // 8 col-groups of 8 cols
    const int ty = tid >> 3;           // 64 row-groups of 2 rows
    const int c0 = tx * 8;
    const int rowBase = blockIdx.x * 128 + ty * 2;
    const int r0 = min(rowBase,     NN - 1);
    const int r1 = min(rowBase + 1, NN - 1);
    const float2* h0 = (const float2*)(H + (size_t)r0 * 128);
    const float2* h1 = (const float2*)(H + (size_t)r1 * 128);

    const u64* sWp = (const u64*)sW;   // 32 pairs per k-row
    const int pb = tx * 4;             // first pair index

    u64 acc0[4] = {0, 0, 0, 0};
    u64 acc1[4] = {0, 0, 0, 0};

    #pragma unroll 2
    for (int k2 = 0; k2 < 64; k2++) {  // two k per iteration
        float2 a0 = __ldg(&h0[k2]);
        float2 a1 = __ldg(&h1[k2]);
        ulonglong2 wa0 = *(const ulonglong2*)&sWp[(2 * k2 + 0) * 32 + pb];
        ulonglong2 wa1 = *(const ulonglong2*)&sWp[(2 * k2 + 0) * 32 + pb + 2];
        ulonglong2 wb0 = *(const ulonglong2*)&sWp[(2 * k2 + 1) * 32 + pb];
        ulonglong2 wb1 = *(const ulonglong2*)&sWp[(2 * k2 + 1) * 32 + pb + 2];

        u64 d;
        DUP_F32X2(d, a0.x);
        FMA_F32X2(acc0[0], d, wa0.x); FMA_F32X2(acc0[1], d, wa0.y);
        FMA_F32X2(acc0[2], d, wa1.x); FMA_F32X2(acc0[3], d, wa1.y);
        DUP_F32X2(d, a0.y);
        FMA_F32X2(acc0[0], d, wb0.x); FMA_F32X2(acc0[1], d, wb0.y);
        FMA_F32X2(acc0[2], d, wb1.x); FMA_F32X2(acc0[3], d, wb1.y);
        DUP_F32X2(d, a1.x);
        FMA_F32X2(acc1[0], d, wa0.x); FMA_F32X2(acc1[1], d, wa0.y);
        FMA_F32X2(acc1[2], d, wa1.x); FMA_F32X2(acc1[3], d, wa1.y);
        DUP_F32X2(d, a1.y);
        FMA_F32X2(acc1[0], d, wb0.x); FMA_F32X2(acc1[1], d, wb0.y);
        FMA_F32X2(acc1[2], d, wb1.x); FMA_F32X2(acc1[3], d, wb1.y);
    }

    if (rowBase < NN) {
        u64* dst = (u64*)(G + (size_t)rowBase * 64 + c0);
        ulonglong2 o0; o0.x = acc0[0]; o0.y = acc0[1];
        ulonglong2 o1; o1.x = acc0[2]; o1.y = acc0[3];
        *(ulonglong2*)(dst)     = o0;
        *(ulonglong2*)(dst + 2) = o1;
    }
    if (rowBase + 1 < NN) {
        u64* dst = (u64*)(G + (size_t)(rowBase + 1) * 64 + c0);
        ulonglong2 o0; o0.x = acc1[0]; o0.y = acc1[1];
        ulonglong2 o1; o1.x = acc1[2]; o1.y = acc1[3];
        *(ulonglong2*)(dst)     = o0;
        *(ulonglong2*)(dst + 2) = o1;
    }
}

// ---------------------------------------------------------------------------
// Segment sum (width 64): one warp per node, atomic-free, 4-wide MLP.
// ---------------------------------------------------------------------------
__global__ void __launch_bounds__(256)
segsum64(const float* __restrict__ G, const int* __restrict__ src,
         float* __restrict__ Out) {
    int gw = (blockIdx.x * 256 + threadIdx.x) >> 5;
    int lane = threadIdx.x & 31;
    if (gw >= NN) return;
    int s = g_rowptr[gw], e = g_rowptr[gw + 1];

    float2 acc0 = make_float2(0, 0), acc1 = make_float2(0, 0);
    float2 acc2 = make_float2(0, 0), acc3 = make_float2(0, 0);
    for (int base = s; base < e; base += 32) {
        int cnt = min(32, e - base);
        int myidx = (base + lane < e) ? __ldg(&src[base + lane]) : 0;
        int j = 0;
        for (; j + 3 < cnt; j += 4) {
            int s0 = __shfl_sync(0xffffffffu, myidx, j);
            int s1 = __shfl_sync(0xffffffffu, myidx, j + 1);
            int s2 = __shfl_sync(0xffffffffu, myidx, j + 2);
            int s3 = __shfl_sync(0xffffffffu, myidx, j + 3);
            float2 x0 = __ldg((const float2*)(G + (size_t)s0 * 64) + lane);
            float2 x1 = __ldg((const float2*)(G + (size_t)s1 * 64) + lane);
            float2 x2 = __ldg((const float2*)(G + (size_t)s2 * 64) + lane);
            float2 x3 = __ldg((const float2*)(G + (size_t)s3 * 64) + lane);
            acc0.x += x0.x; acc0.y += x0.y;
            acc1.x += x1.x; acc1.y += x1.y;
            acc2.x += x2.x; acc2.y += x2.y;
            acc3.x += x3.x; acc3.y += x3.y;
        }
        for (; j < cnt; j++) {
            int s0 = __shfl_sync(0xffffffffu, myidx, j);
            float2 x0 = __ldg((const float2*)(G + (size_t)s0 * 64) + lane);
            acc0.x += x0.x; acc0.y += x0.y;
        }
    }
    float2 o = make_float2((acc0.x + acc1.x) + (acc2.x + acc3.x),
                           (acc0.y + acc1.y) + (acc2.y + acc3.y));
    *((float2*)(Out + (size_t)gw * 64) + lane) = o;
}

// ---------------------------------------------------------------------------
// Launch.  out = S^3 (F @ (W1 @ (W2 @ W3)))
// ---------------------------------------------------------------------------
extern "C" void kernel_launch(void* const* d_in, const int* in_sizes, int n_in,
                              void* d_out, int out_size) {
    const int*   src  = (const int*)d_in[0];
    const int*   dst  = (const int*)d_in[1];
    const float* feat = (const float*)d_in[2];
    const float* W1   = (const float*)d_in[3];
    const float* W2   = (const float*)d_in[4];
    const float* W3   = (const float*)d_in[5];
    float* out = (float*)d_out;

    float *gb, *hb, *w23, *w123;
    cudaGetSymbolAddress((void**)&gb,   g_buf);
    cudaGetSymbolAddress((void**)&hb,   h_buf);
    cudaGetSymbolAddress((void**)&w23,  w23_buf);
    cudaGetSymbolAddress((void**)&w123, w123_buf);

    const int GEMM_BLOCKS = (NN + 127) / 128;  // 313
    const int SEG_BLOCKS  = NN / 8;            // 5000

    build_rowptr<<<(NN + 1 + 255) / 256, 256>>>(dst);

    // W123 = W1 @ (W2 @ W3)
    mm128x64<<<32, 256>>>(W2, W3, w23);
    mm128x64<<<32, 256>>>(W1, w23, w123);

    // X = F @ W123
    gemm64<<<GEMM_BLOCKS, 512>>>(feat, w123, gb);

    // out = S^3 X
    segsum64<<<SEG_BLOCKS, 256>>>(gb, src, hb);
    segsum64<<<SEG_BLOCKS, 256>>>(hb, src, gb);
    segsum64<<<SEG_BLOCKS, 256>>>(gb, src, out);
}

// round 6
// speedup vs baseline: 1.3797x; 1.3797x over previous
#include <cuda_runtime.h>
#include <cstdint>

#define NN 40000
#define NE 640000

// ---- device scratch ----
__device__ __align__(128) float g_buf[NN * 64];
__device__ __align__(128) float h_buf[NN * 64];
__device__ __align__(128) float w23_buf[128 * 64];
__device__ __align__(128) float w123_buf[128 * 64];
__device__ int g_rowptr[NN + 1];

typedef unsigned long long u64;

#define FMA_F32X2(d, a, b) \
    asm("fma.rn.f32x2 %0, %1, %2, %0;" : "+l"(d) : "l"(a), "l"(b))
#define DUP_F32X2(d, f) \
    asm("mov.b64 %0, {%1, %1};" : "=l"(d) : "r"(__float_as_uint(f)))

// ---------------------------------------------------------------------------
// CSR row pointers from SORTED dst: row_ptr[n] = lower_bound(dst, n)
// ---------------------------------------------------------------------------
__global__ void build_rowptr(const int* __restrict__ dst) {
    int n = blockIdx.x * blockDim.x + threadIdx.x;
    if (n > NN) return;
    int lo = 0, hi = NE;
    while (lo < hi) {
        int mid = (lo + hi) >> 1;
        if (dst[mid] < n) lo = mid + 1; else hi = mid;
    }
    g_rowptr[n] = lo;
}

// ---------------------------------------------------------------------------
// Small matmul C[128,64] = A[128,128] @ B[128,64], B staged in smem.
// ---------------------------------------------------------------------------
__global__ void __launch_bounds__(256)
mm128x64(const float* __restrict__ A, const float* __restrict__ B,
         float* __restrict__ C) {
    __shared__ float sB[128 * 64];
    int tid = threadIdx.x;
    for (int i = tid * 4; i < 128 * 64; i += 256 * 4)
        *(float4*)&sB[i] = *(const float4*)&B[i];
    __syncthreads();

    int idx = blockIdx.x * 256 + tid;
    int i = idx >> 6, j = idx & 63;
    float acc = 0.f;
    #pragma unroll 8
    for (int k = 0; k < 128; k++)
        acc += __ldg(&A[i * 128 + k]) * sB[k * 64 + j];
    C[idx] = acc;
}

// ---------------------------------------------------------------------------
// GEMM: X[N,64] = F[N,128] @ W[128,64], packed fma.rn.f32x2.
// R4 microtile (known-good): 256 threads, 8 rows x 4 cols per thread
// (16 f32x2-FMA per LDS.128 — keeps smem crossbar sub-critical).
// Change vs R4: launch_bounds(256,3) -> regs<=80, 3 CTAs/SM = 24 warps.
// ---------------------------------------------------------------------------
__global__ void __launch_bounds__(256, 3)
gemm64(const float* __restrict__ H, const float* __restrict__ W,
       float* __restrict__ G) {
    __shared__ float sW[128 * 64];

    const int tid = threadIdx.x;
    #pragma unroll
    for (int i = tid * 4; i < 128 * 64; i += 256 * 4)
        *(float4*)&sW[i] = *(const float4*)&W[i];
    __syncthreads();

    constexpr int NP = 2;              // 2 f32x2 pairs = 4 cols
    const int tx = tid & 15, ty = tid >> 4;
    const int rowBase = blockIdx.x * 128 + ty * 8;
    const int c0 = tx * 4;

    const float2* hp[8];
    #pragma unroll
    for (int i = 0; i < 8; i++) {
        int r = rowBase + i;
        if (r >= NN) r = NN - 1;
        hp[i] = (const float2*)(H + (size_t)r * 128);
    }

    const u64* sWp = (const u64*)sW;   // 32 pairs per k-row
    const int pbase = c0 >> 1;

    u64 acc[8][NP];
    #pragma unroll
    for (int i = 0; i < 8; i++)
        #pragma unroll
        for (int j = 0; j < NP; j++) acc[i][j] = 0ull;

    #pragma unroll 4
    for (int k2 = 0; k2 < 64; k2++) {  // two k per iteration
        float2 a[8];
        #pragma unroll
        for (int i = 0; i < 8; i++) a[i] = __ldg(&hp[i][k2]);

        ulonglong2 v0 = *(const ulonglong2*)&sWp[(2 * k2 + 0) * 32 + pbase];
        ulonglong2 v1 = *(const ulonglong2*)&sWp[(2 * k2 + 1) * 32 + pbase];

        #pragma unroll
        for (int i = 0; i < 8; i++) {
            u64 a2;
            DUP_F32X2(a2, a[i].x);
            FMA_F32X2(acc[i][0], a2, v0.x);
            FMA_F32X2(acc[i][1], a2, v0.y);
        }
        #pragma unroll
        for (int i = 0; i < 8; i++) {
            u64 a2;
            DUP_F32X2(a2, a[i].y);
            FMA_F32X2(acc[i][0], a2, v1.x);
            FMA_F32X2(acc[i][1], a2, v1.y);
        }
    }

    #pragma unroll
    for (int i = 0; i < 8; i++) {
        int grow = rowBase + i;
        if (grow < NN) {
            ulonglong2 o; o.x = acc[i][0]; o.y = acc[i][1];
            *(ulonglong2*)(G + (size_t)grow * 64 + c0) = o;
        }
    }
}

// ---------------------------------------------------------------------------
// Segment sum (width 64): one warp per node, atomic-free, 4-wide MLP.
// ---------------------------------------------------------------------------
__global__ void __launch_bounds__(256)
segsum64(const float* __restrict__ G, const int* __restrict__ src,
         float* __restrict__ Out) {
    int gw = (blockIdx.x * 256 + threadIdx.x) >> 5;
    int lane = threadIdx.x & 31;
    if (gw >= NN) return;
    int s = g_rowptr[gw], e = g_rowptr[gw + 1];

    float2 acc0 = make_float2(0, 0), acc1 = make_float2(0, 0);
    float2 acc2 = make_float2(0, 0), acc3 = make_float2(0, 0);
    for (int base = s; base < e; base += 32) {
        int cnt = min(32, e - base);
        int myidx = (base + lane < e) ? __ldg(&src[base + lane]) : 0;
        int j = 0;
        for (; j + 3 < cnt; j += 4) {
            int s0 = __shfl_sync(0xffffffffu, myidx, j);
            int s1 = __shfl_sync(0xffffffffu, myidx, j + 1);
            int s2 = __shfl_sync(0xffffffffu, myidx, j + 2);
            int s3 = __shfl_sync(0xffffffffu, myidx, j + 3);
            float2 x0 = __ldg((const float2*)(G + (size_t)s0 * 64) + lane);
            float2 x1 = __ldg((const float2*)(G + (size_t)s1 * 64) + lane);
            float2 x2 = __ldg((const float2*)(G + (size_t)s2 * 64) + lane);
            float2 x3 = __ldg((const float2*)(G + (size_t)s3 * 64) + lane);
            acc0.x += x0.x; acc0.y += x0.y;
            acc1.x += x1.x; acc1.y += x1.y;
            acc2.x += x2.x; acc2.y += x2.y;
            acc3.x += x3.x; acc3.y += x3.y;
        }
        for (; j < cnt; j++) {
            int s0 = __shfl_sync(0xffffffffu, myidx, j);
            float2 x0 = __ldg((const float2*)(G + (size_t)s0 * 64) + lane);
            acc0.x += x0.x; acc0.y += x0.y;
        }
    }
    float2 o = make_float2((acc0.x + acc1.x) + (acc2.x + acc3.x),
                           (acc0.y + acc1.y) + (acc2.y + acc3.y));
    *((float2*)(Out + (size_t)gw * 64) + lane) = o;
}

// ---------------------------------------------------------------------------
// Launch.  out = S^3 (F @ (W1 @ (W2 @ W3)))
// ---------------------------------------------------------------------------
extern "C" void kernel_launch(void* const* d_in, const int* in_sizes, int n_in,
                              void* d_out, int out_size) {
    const int*   src  = (const int*)d_in[0];
    const int*   dst  = (const int*)d_in[1];
    const float* feat = (const float*)d_in[2];
    const float* W1   = (const float*)d_in[3];
    const float* W2   = (const float*)d_in[4];
    const float* W3   = (const float*)d_in[5];
    float* out = (float*)d_out;

    float *gb, *hb, *w23, *w123;
    cudaGetSymbolAddress((void**)&gb,   g_buf);
    cudaGetSymbolAddress((void**)&hb,   h_buf);
    cudaGetSymbolAddress((void**)&w23,  w23_buf);
    cudaGetSymbolAddress((void**)&w123, w123_buf);

    const int GEMM_BLOCKS = (NN + 127) / 128;  // 313
    const int SEG_BLOCKS  = NN / 8;            // 5000

    build_rowptr<<<(NN + 1 + 255) / 256, 256>>>(dst);

    // W123 = W1 @ (W2 @ W3)
    mm128x64<<<32, 256>>>(W2, W3, w23);
    mm128x64<<<32, 256>>>(W1, w23, w123);

    // X = F @ W123
    gemm64<<<GEMM_BLOCKS, 256>>>(feat, w123, gb);

    // out = S^3 X
    segsum64<<<SEG_BLOCKS, 256>>>(gb, src, hb);
    segsum64<<<SEG_BLOCKS, 256>>>(hb, src, gb);
    segsum64<<<SEG_BLOCKS, 256>>>(gb, src, out);
}

// round 7
// speedup vs baseline: 1.7184x; 1.2455x over previous
#include <cuda_runtime.h>
#include <cuda_bf16.h>
#include <cstdint>

#define NN 40000
#define NE 640000

// ---- device scratch ----
__device__ __align__(128) float g_buf[NN * 64];
__device__ __align__(128) float h_buf[NN * 64];
__device__ __align__(128) float w23_buf[128 * 64];
__device__ __align__(128) float w123_buf[128 * 64];
__device__ __align__(128) uint2 bph_buf[2048];   // packed B frags, hi
__device__ __align__(128) uint2 bpl_buf[2048];   // packed B frags, lo
__device__ int g_rowptr[NN + 1];

// ---------------------------------------------------------------------------
// CSR row pointers from SORTED dst
// ---------------------------------------------------------------------------
__global__ void build_rowptr(const int* __restrict__ dst) {
    int n = blockIdx.x * blockDim.x + threadIdx.x;
    if (n > NN) return;
    int lo = 0, hi = NE;
    while (lo < hi) {
        int mid = (lo + hi) >> 1;
        if (dst[mid] < n) lo = mid + 1; else hi = mid;
    }
    g_rowptr[n] = lo;
}

// ---------------------------------------------------------------------------
// Small matmul C[128,64] = A[128,128] @ B[128,64], B staged in smem.
// ---------------------------------------------------------------------------
__global__ void __launch_bounds__(256)
mm128x64(const float* __restrict__ A, const float* __restrict__ B,
         float* __restrict__ C) {
    __shared__ float sB[128 * 64];
    int tid = threadIdx.x;
    for (int i = tid * 4; i < 128 * 64; i += 256 * 4)
        *(float4*)&sB[i] = *(const float4*)&B[i];
    __syncthreads();

    int idx = blockIdx.x * 256 + tid;
    int i = idx >> 6, j = idx & 63;
    float acc = 0.f;
    #pragma unroll 8
    for (int k = 0; k < 128; k++)
        acc += __ldg(&A[i * 128 + k]) * sB[k * 64 + j];
    C[idx] = acc;
}

// ---------------------------------------------------------------------------
// Pack W123[128,64] into m16n8k16 B fragments (col-major B), bf16 hi/lo.
// Fragment map (PTX ISA, mma.m16n8k16.row.col):
//   lane = 4*g' pattern: g = lane>>2 (col within n-tile), tig = lane&3
//   b0 = bf16x2 (k = c*16 + 2*tig, +1 | col)
//   b1 = bf16x2 (k = c*16 + 8 + 2*tig, +1 | col)
// Index: [t(n-tile 0..7)][c(k-chunk 0..7)][lane] -> uint2{b0,b1}
// ---------------------------------------------------------------------------
__global__ void __launch_bounds__(256)
wpack(const float* __restrict__ W, uint2* __restrict__ BPH,
      uint2* __restrict__ BPL) {
    int idx = blockIdx.x * 256 + threadIdx.x;   // 0..2047
    if (idx >= 2048) return;
    int lane = idx & 31, c = (idx >> 5) & 7, t = idx >> 8;
    int g = lane >> 2, tig = lane & 3;
    int n = t * 8 + g;
    int k0 = c * 16 + 2 * tig;

    float x0 = W[(k0 + 0) * 64 + n], x1 = W[(k0 + 1) * 64 + n];
    float x2 = W[(k0 + 8) * 64 + n], x3 = W[(k0 + 9) * 64 + n];

    __nv_bfloat162 h01 = __floats2bfloat162_rn(x0, x1);
    __nv_bfloat162 h23 = __floats2bfloat162_rn(x2, x3);
    float2 b01 = __bfloat1622float2(h01);
    float2 b23 = __bfloat1622float2(h23);
    __nv_bfloat162 l01 = __floats2bfloat162_rn(x0 - b01.x, x1 - b01.y);
    __nv_bfloat162 l23 = __floats2bfloat162_rn(x2 - b23.x, x3 - b23.y);

    BPH[idx] = make_uint2(*(uint32_t*)&h01, *(uint32_t*)&h23);
    BPL[idx] = make_uint2(*(uint32_t*)&l01, *(uint32_t*)&l23);
}

// ---------------------------------------------------------------------------
// HMMA GEMM: X[N,64] = F[N,128] @ W123[128,64] via mma.sync m16n8k16
// bf16 3-term split (AhBh + AlBh + AhBl), fp32 accumulate.
// 8 warps/block, 16 rows/warp -> 128 rows/block. A split done in registers.
// ---------------------------------------------------------------------------
#define MMA_BF16(c0, c1, c2, c3, a0, a1, a2, a3, b0, b1)                     \
    asm volatile(                                                            \
        "mma.sync.aligned.m16n8k16.row.col.f32.bf16.bf16.f32 "               \
        "{%0,%1,%2,%3}, {%4,%5,%6,%7}, {%8,%9}, {%0,%1,%2,%3};"              \
        : "+f"(c0), "+f"(c1), "+f"(c2), "+f"(c3)                             \
        : "r"(a0), "r"(a1), "r"(a2), "r"(a3), "r"(b0), "r"(b1))

__device__ __forceinline__ void split2(float2 v, uint32_t& h, uint32_t& l) {
    __nv_bfloat162 hh = __floats2bfloat162_rn(v.x, v.y);
    float2 b = __bfloat1622float2(hh);
    __nv_bfloat162 ll = __floats2bfloat162_rn(v.x - b.x, v.y - b.y);
    h = *(uint32_t*)&hh; l = *(uint32_t*)&ll;
}

__global__ void __launch_bounds__(256)
gemm_mma(const float* __restrict__ F, const uint2* __restrict__ BPH,
         const uint2* __restrict__ BPL, float* __restrict__ G) {
    __shared__ uint2 sBh[2048];
    __shared__ uint2 sBl[2048];
    const int tid = threadIdx.x;

    // Stage packed B frags (32KB total) — uint4 copies
    {
        const uint4* sh = (const uint4*)BPH;
        const uint4* sl = (const uint4*)BPL;
        uint4* dh = (uint4*)sBh; uint4* dl = (uint4*)sBl;
        #pragma unroll
        for (int i = tid; i < 1024; i += 256) { dh[i] = sh[i]; dl[i] = sl[i]; }
    }
    __syncthreads();

    const int warp = tid >> 5, lane = tid & 31;
    const int g = lane >> 2, tig = lane & 3;
    const int rowBase = blockIdx.x * 128 + warp * 16;
    const int rlo = min(rowBase + g,     NN - 1);
    const int rhi = min(rowBase + g + 8, NN - 1);
    const float2* flo = (const float2*)(F + (size_t)rlo * 128);
    const float2* fhi = (const float2*)(F + (size_t)rhi * 128);

    float acc[8][4];
    #pragma unroll
    for (int t = 0; t < 8; t++)
        #pragma unroll
        for (int j = 0; j < 4; j++) acc[t][j] = 0.f;

    #pragma unroll
    for (int c = 0; c < 8; c++) {
        // A fragment loads (fp32) + in-register bf16 hi/lo split
        float2 v0 = __ldg(&flo[c * 8 + tig]);        // (row g,   k 2tig..)
        float2 v1 = __ldg(&fhi[c * 8 + tig]);        // (row g+8, k 2tig..)
        float2 v2 = __ldg(&flo[c * 8 + tig + 4]);    // (row g,   k 2tig+8..)
        float2 v3 = __ldg(&fhi[c * 8 + tig + 4]);    // (row g+8, k 2tig+8..)
        uint32_t ah0, ah1, ah2, ah3, al0, al1, al2, al3;
        split2(v0, ah0, al0); split2(v1, ah1, al1);
        split2(v2, ah2, al2); split2(v3, ah3, al3);

        #pragma unroll
        for (int t = 0; t < 8; t++) {
            uint2 bh = sBh[(t * 8 + c) * 32 + lane];
            uint2 bl = sBl[(t * 8 + c) * 32 + lane];
            MMA_BF16(acc[t][0], acc[t][1], acc[t][2], acc[t][3],
                     ah0, ah1, ah2, ah3, bh.x, bh.y);
            MMA_BF16(acc[t][0], acc[t][1], acc[t][2], acc[t][3],
                     al0, al1, al2, al3, bh.x, bh.y);
            MMA_BF16(acc[t][0], acc[t][1], acc[t][2], acc[t][3],
                     ah0, ah1, ah2, ah3, bl.x, bl.y);
        }
    }

    // Epilogue: c0,c1 -> (row g, cols 2tig,2tig+1); c2,c3 -> row g+8
    const int rA = rowBase + g, rB = rowBase + g + 8;
    #pragma unroll
    for (int t = 0; t < 8; t++) {
        int col = t * 8 + 2 * tig;
        if (rA < NN)
            *(float2*)(G + (size_t)rA * 64 + col) = make_float2(acc[t][0], acc[t][1]);
        if (rB < NN)
            *(float2*)(G + (size_t)rB * 64 + col) = make_float2(acc[t][2], acc[t][3]);
    }
}

// ---------------------------------------------------------------------------
// Segment sum (width 64): one warp per node, atomic-free, 4-wide MLP.
// ---------------------------------------------------------------------------
__global__ void __launch_bounds__(256)
segsum64(const float* __restrict__ G, const int* __restrict__ src,
         float* __restrict__ Out) {
    int gw = (blockIdx.x * 256 + threadIdx.x) >> 5;
    int lane = threadIdx.x & 31;
    if (gw >= NN) return;
    int s = g_rowptr[gw], e = g_rowptr[gw + 1];

    float2 acc0 = make_float2(0, 0), acc1 = make_float2(0, 0);
    float2 acc2 = make_float2(0, 0), acc3 = make_float2(0, 0);
    for (int base = s; base < e; base += 32) {
        int cnt = min(32, e - base);
        int myidx = (base + lane < e) ? __ldg(&src[base + lane]) : 0;
        int j = 0;
        for (; j + 3 < cnt; j += 4) {
            int s0 = __shfl_sync(0xffffffffu, myidx, j);
            int s1 = __shfl_sync(0xffffffffu, myidx, j + 1);
            int s2 = __shfl_sync(0xffffffffu, myidx, j + 2);
            int s3 = __shfl_sync(0xffffffffu, myidx, j + 3);
            float2 x0 = __ldg((const float2*)(G + (size_t)s0 * 64) + lane);
            float2 x1 = __ldg((const float2*)(G + (size_t)s1 * 64) + lane);
            float2 x2 = __ldg((const float2*)(G + (size_t)s2 * 64) + lane);
            float2 x3 = __ldg((const float2*)(G + (size_t)s3 * 64) + lane);
            acc0.x += x0.x; acc0.y += x0.y;
            acc1.x += x1.x; acc1.y += x1.y;
            acc2.x += x2.x; acc2.y += x2.y;
            acc3.x += x3.x; acc3.y += x3.y;
        }
        for (; j < cnt; j++) {
            int s0 = __shfl_sync(0xffffffffu, myidx, j);
            float2 x0 = __ldg((const float2*)(G + (size_t)s0 * 64) + lane);
            acc0.x += x0.x; acc0.y += x0.y;
        }
    }
    float2 o = make_float2((acc0.x + acc1.x) + (acc2.x + acc3.x),
                           (acc0.y + acc1.y) + (acc2.y + acc3.y));
    *((float2*)(Out + (size_t)gw * 64) + lane) = o;
}

// ---------------------------------------------------------------------------
// Launch.  out = S^3 (F @ (W1 @ (W2 @ W3)))
// ---------------------------------------------------------------------------
extern "C" void kernel_launch(void* const* d_in, const int* in_sizes, int n_in,
                              void* d_out, int out_size) {
    const int*   src  = (const int*)d_in[0];
    const int*   dst  = (const int*)d_in[1];
    const float* feat = (const float*)d_in[2];
    const float* W1   = (const float*)d_in[3];
    const float* W2   = (const float*)d_in[4];
    const float* W3   = (const float*)d_in[5];
    float* out = (float*)d_out;

    float *gb, *hb, *w23, *w123; uint2 *bph, *bpl;
    cudaGetSymbolAddress((void**)&gb,   g_buf);
    cudaGetSymbolAddress((void**)&hb,   h_buf);
    cudaGetSymbolAddress((void**)&w23,  w23_buf);
    cudaGetSymbolAddress((void**)&w123, w123_buf);
    cudaGetSymbolAddress((void**)&bph,  bph_buf);
    cudaGetSymbolAddress((void**)&bpl,  bpl_buf);

    const int GEMM_BLOCKS = (NN + 127) / 128;  // 313
    const int SEG_BLOCKS  = NN / 8;            // 5000

    build_rowptr<<<(NN + 1 + 255) / 256, 256>>>(dst);

    // W123 = W1 @ (W2 @ W3), then pack into mma B fragments (hi/lo)
    mm128x64<<<32, 256>>>(W2, W3, w23);
    mm128x64<<<32, 256>>>(W1, w23, w123);
    wpack<<<8, 256>>>(w123, bph, bpl);

    // X = F @ W123 (HMMA, bf16 split)
    gemm_mma<<<GEMM_BLOCKS, 256>>>(feat, bph, bpl, gb);

    // out = S^3 X
    segsum64<<<SEG_BLOCKS, 256>>>(gb, src, hb);
    segsum64<<<SEG_BLOCKS, 256>>>(hb, src, gb);
    segsum64<<<SEG_BLOCKS, 256>>>(gb, src, out);
}

// round 8
// speedup vs baseline: 2.0186x; 1.1747x over previous
#include <cuda_runtime.h>
#include <cuda_bf16.h>
#include <cstdint>

#define NN 40000
#define NE 640000

// ---- device scratch ----
__device__ __align__(128) float g_buf[NN * 64];
__device__ __align__(128) float h_buf[NN * 64];
__device__ __align__(128) uint2 bph_buf[2048];   // packed B frags, hi
__device__ __align__(128) uint2 bpl_buf[2048];   // packed B frags, lo
__device__ int g_rowptr[NN + 1];

// ---------------------------------------------------------------------------
// Fused prep kernel.
//  blocks [0, 313):   CSR row pointers from SORTED dst (lower_bound)
//  blocks [313, 377): per-output-column W chain: W123[:,n] = W1@(W2@W3[:,n]),
//                     then pack that column's 32 mma B-fragment entries
//                     (bf16 hi/lo split) straight into BPH/BPL.
// Fragment map (mma.m16n8k16.row.col, B col-major):
//   entry idx = (t*8 + c)*32 + g*4 + tig, where n = t*8+g, k0 = c*16+2*tig,
//   uint2 = { bf16x2(w[k0],w[k0+1]), bf16x2(w[k0+8],w[k0+9]) }.
// ---------------------------------------------------------------------------
__global__ void __launch_bounds__(128)
prep(const int* __restrict__ dst, const float* __restrict__ W1,
     const float* __restrict__ W2, const float* __restrict__ W3,
     uint2* __restrict__ BPH, uint2* __restrict__ BPL) {
    const int b = blockIdx.x, tid = threadIdx.x;

    if (b < 313) {                      // ---- rowptr part ----
        int n = b * 128 + tid;
        if (n > NN) return;
        int lo = 0, hi = NE;
        while (lo < hi) {
            int mid = (lo + hi) >> 1;
            if (dst[mid] < n) lo = mid + 1; else hi = mid;
        }
        g_rowptr[n] = lo;
        return;
    }

    // ---- W-chain part: one block per column n ----
    const int n = b - 313;              // 0..63
    __shared__ float v[128], u[128], w[128];

    v[tid] = __ldg(&W3[tid * 64 + n]);
    __syncthreads();

    {   // u = W2 @ v  (thread tid -> u[tid]; row read float4, v broadcast)
        const float4* row = (const float4*)(W2 + tid * 128);
        float acc = 0.f;
        #pragma unroll
        for (int k = 0; k < 32; k++) {
            float4 a = __ldg(&row[k]);
            acc += a.x * v[4 * k] + a.y * v[4 * k + 1] +
                   a.z * v[4 * k + 2] + a.w * v[4 * k + 3];
        }
        u[tid] = acc;
    }
    __syncthreads();

    {   // w = W1 @ u
        const float4* row = (const float4*)(W1 + tid * 128);
        float acc = 0.f;
        #pragma unroll
        for (int k = 0; k < 32; k++) {
            float4 a = __ldg(&row[k]);
            acc += a.x * u[4 * k] + a.y * u[4 * k + 1] +
                   a.z * u[4 * k + 2] + a.w * u[4 * k + 3];
        }
        w[tid] = acc;
    }
    __syncthreads();

    if (tid < 32) {                     // pack this column's 32 frag entries
        int c = tid >> 2, tig = tid & 3;
        int k0 = c * 16 + 2 * tig;
        float x0 = w[k0], x1 = w[k0 + 1], x2 = w[k0 + 8], x3 = w[k0 + 9];

        __nv_bfloat162 h01 = __floats2bfloat162_rn(x0, x1);
        __nv_bfloat162 h23 = __floats2bfloat162_rn(x2, x3);
        float2 b01 = __bfloat1622float2(h01);
        float2 b23 = __bfloat1622float2(h23);
        __nv_bfloat162 l01 = __floats2bfloat162_rn(x0 - b01.x, x1 - b01.y);
        __nv_bfloat162 l23 = __floats2bfloat162_rn(x2 - b23.x, x3 - b23.y);

        int t = n >> 3, g = n & 7;
        int idx = (t * 8 + c) * 32 + g * 4 + tig;
        BPH[idx] = make_uint2(*(uint32_t*)&h01, *(uint32_t*)&h23);
        BPL[idx] = make_uint2(*(uint32_t*)&l01, *(uint32_t*)&l23);
    }
}

// ---------------------------------------------------------------------------
// HMMA GEMM: X[N,64] = F[N,128] @ W123[128,64] via mma.sync m16n8k16
// bf16 3-term split (AhBh + AlBh + AhBl), fp32 accumulate.
// 8 warps/block, 16 rows/warp -> 128 rows/block. A split done in registers.
// ---------------------------------------------------------------------------
#define MMA_BF16(c0, c1, c2, c3, a0, a1, a2, a3, b0, b1)                     \
    asm volatile(                                                            \
        "mma.sync.aligned.m16n8k16.row.col.f32.bf16.bf16.f32 "               \
        "{%0,%1,%2,%3}, {%4,%5,%6,%7}, {%8,%9}, {%0,%1,%2,%3};"              \
        : "+f"(c0), "+f"(c1), "+f"(c2), "+f"(c3)                             \
        : "r"(a0), "r"(a1), "r"(a2), "r"(a3), "r"(b0), "r"(b1))

__device__ __forceinline__ void split2(float2 v, uint32_t& h, uint32_t& l) {
    __nv_bfloat162 hh = __floats2bfloat162_rn(v.x, v.y);
    float2 b = __bfloat1622float2(hh);
    __nv_bfloat162 ll = __floats2bfloat162_rn(v.x - b.x, v.y - b.y);
    h = *(uint32_t*)&hh; l = *(uint32_t*)&ll;
}

__global__ void __launch_bounds__(256)
gemm_mma(const float* __restrict__ F, const uint2* __restrict__ BPH,
         const uint2* __restrict__ BPL, float* __restrict__ G) {
    __shared__ uint2 sBh[2048];
    __shared__ uint2 sBl[2048];
    const int tid = threadIdx.x;

    {   // Stage packed B frags (32KB) — uint4 copies
        const uint4* sh = (const uint4*)BPH;
        const uint4* sl = (const uint4*)BPL;
        uint4* dh = (uint4*)sBh; uint4* dl = (uint4*)sBl;
        #pragma unroll
        for (int i = tid; i < 1024; i += 256) { dh[i] = sh[i]; dl[i] = sl[i]; }
    }
    __syncthreads();

    const int warp = tid >> 5, lane = tid & 31;
    const int g = lane >> 2, tig = lane & 3;
    const int rowBase = blockIdx.x * 128 + warp * 16;
    const int rlo = min(rowBase + g,     NN - 1);
    const int rhi = min(rowBase + g + 8, NN - 1);
    const float2* flo = (const float2*)(F + (size_t)rlo * 128);
    const float2* fhi = (const float2*)(F + (size_t)rhi * 128);

    float acc[8][4];
    #pragma unroll
    for (int t = 0; t < 8; t++)
        #pragma unroll
        for (int j = 0; j < 4; j++) acc[t][j] = 0.f;

    #pragma unroll
    for (int c = 0; c < 8; c++) {
        float2 v0 = __ldg(&flo[c * 8 + tig]);
        float2 v1 = __ldg(&fhi[c * 8 + tig]);
        float2 v2 = __ldg(&flo[c * 8 + tig + 4]);
        float2 v3 = __ldg(&fhi[c * 8 + tig + 4]);
        uint32_t ah0, ah1, ah2, ah3, al0, al1, al2, al3;
        split2(v0, ah0, al0); split2(v1, ah1, al1);
        split2(v2, ah2, al2); split2(v3, ah3, al3);

        #pragma unroll
        for (int t = 0; t < 8; t++) {
            uint2 bh = sBh[(t * 8 + c) * 32 + lane];
            uint2 bl = sBl[(t * 8 + c) * 32 + lane];
            MMA_BF16(acc[t][0], acc[t][1], acc[t][2], acc[t][3],
                     ah0, ah1, ah2, ah3, bh.x, bh.y);
            MMA_BF16(acc[t][0], acc[t][1], acc[t][2], acc[t][3],
                     al0, al1, al2, al3, bh.x, bh.y);
            MMA_BF16(acc[t][0], acc[t][1], acc[t][2], acc[t][3],
                     ah0, ah1, ah2, ah3, bl.x, bl.y);
        }
    }

    const int rA = rowBase + g, rB = rowBase + g + 8;
    #pragma unroll
    for (int t = 0; t < 8; t++) {
        int col = t * 8 + 2 * tig;
        if (rA < NN)
            *(float2*)(G + (size_t)rA * 64 + col) = make_float2(acc[t][0], acc[t][1]);
        if (rB < NN)
            *(float2*)(G + (size_t)rB * 64 + col) = make_float2(acc[t][2], acc[t][3]);
    }
}

// ---------------------------------------------------------------------------
// Segment sum (width 64): one warp per node, atomic-free, 4-wide MLP.
// ---------------------------------------------------------------------------
__global__ void __launch_bounds__(256)
segsum64(const float* __restrict__ G, const int* __restrict__ src,
         float* __restrict__ Out) {
    int gw = (blockIdx.x * 256 + threadIdx.x) >> 5;
    int lane = threadIdx.x & 31;
    if (gw >= NN) return;
    int s = g_rowptr[gw], e = g_rowptr[gw + 1];

    float2 acc0 = make_float2(0, 0), acc1 = make_float2(0, 0);
    float2 acc2 = make_float2(0, 0), acc3 = make_float2(0, 0);
    for (int base = s; base < e; base += 32) {
        int cnt = min(32, e - base);
        int myidx = (base + lane < e) ? __ldg(&src[base + lane]) : 0;
        int j = 0;
        for (; j + 3 < cnt; j += 4) {
            int s0 = __shfl_sync(0xffffffffu, myidx, j);
            int s1 = __shfl_sync(0xffffffffu, myidx, j + 1);
            int s2 = __shfl_sync(0xffffffffu, myidx, j + 2);
            int s3 = __shfl_sync(0xffffffffu, myidx, j + 3);
            float2 x0 = __ldg((const float2*)(G + (size_t)s0 * 64) + lane);
            float2 x1 = __ldg((const float2*)(G + (size_t)s1 * 64) + lane);
            float2 x2 = __ldg((const float2*)(G + (size_t)s2 * 64) + lane);
            float2 x3 = __ldg((const float2*)(G + (size_t)s3 * 64) + lane);
            acc0.x += x0.x; acc0.y += x0.y;
            acc1.x += x1.x; acc1.y += x1.y;
            acc2.x += x2.x; acc2.y += x2.y;
            acc3.x += x3.x; acc3.y += x3.y;
        }
        for (; j < cnt; j++) {
            int s0 = __shfl_sync(0xffffffffu, myidx, j);
            float2 x0 = __ldg((const float2*)(G + (size_t)s0 * 64) + lane);
            acc0.x += x0.x; acc0.y += x0.y;
        }
    }
    float2 o = make_float2((acc0.x + acc1.x) + (acc2.x + acc3.x),
                           (acc0.y + acc1.y) + (acc2.y + acc3.y));
    *((float2*)(Out + (size_t)gw * 64) + lane) = o;
}

// ---------------------------------------------------------------------------
// Launch.  out = S^3 (F @ (W1 @ (W2 @ W3)))   — 5 kernels total
// ---------------------------------------------------------------------------
extern "C" void kernel_launch(void* const* d_in, const int* in_sizes, int n_in,
                              void* d_out, int out_size) {
    const int*   src  = (const int*)d_in[0];
    const int*   dst  = (const int*)d_in[1];
    const float* feat = (const float*)d_in[2];
    const float* W1   = (const float*)d_in[3];
    const float* W2   = (const float*)d_in[4];
    const float* W3   = (const float*)d_in[5];
    float* out = (float*)d_out;

    float *gb, *hb; uint2 *bph, *bpl;
    cudaGetSymbolAddress((void**)&gb,  g_buf);
    cudaGetSymbolAddress((void**)&hb,  h_buf);
    cudaGetSymbolAddress((void**)&bph, bph_buf);
    cudaGetSymbolAddress((void**)&bpl, bpl_buf);

    const int GEMM_BLOCKS = (NN + 127) / 128;  // 313
    const int SEG_BLOCKS  = NN / 8;            // 5000

    // rowptr (313 blocks) + W-chain/pack (64 blocks), fused
    prep<<<313 + 64, 128>>>(dst, W1, W2, W3, bph, bpl);

    // X = F @ W123 (HMMA, bf16 split)
    gemm_mma<<<GEMM_BLOCKS, 256>>>(feat, bph, bpl, gb);

    // out = S^3 X
    segsum64<<<SEG_BLOCKS, 256>>>(gb, src, hb);
    segsum64<<<SEG_BLOCKS, 256>>>(hb, src, gb);
    segsum64<<<SEG_BLOCKS, 256>>>(gb, src, out);
}